// round 14
// baseline (speedup 1.0000x reference)
#include <cuda_runtime.h>
#include <cuda_fp16.h>
#include <cstdint>

#define SEQ 2048
#define BATCH 4
#define EMB 1024
#define NHEAD 16
#define HDIM 64
#define LOG2E 1.4426950408889634f

// scratch (static device arrays: allocation-free rule)
__device__ __half g_q[BATCH*NHEAD*SEQ*HDIM];
__device__ __half g_k[BATCH*NHEAD*SEQ*HDIM];
__device__ __half g_v[BATCH*NHEAD*SEQ*HDIM];
__device__ __half g_attn[SEQ*BATCH*EMB];
__device__ __half g_qr [SEQ*BATCH*EMB];
__device__ __half g_winr[3*EMB*EMB];
__device__ __half g_woutr[EMB*EMB];
__device__ __half g_maskh[BATCH*SEQ*SEQ];   // pad-folded, pre-scaled by log2e

// ---- mma.sync / ldmatrix helpers ----
__device__ __forceinline__ void mma16(float* c, const uint32_t* a, const uint32_t* b) {
    asm volatile(
        "mma.sync.aligned.m16n8k16.row.col.f32.f16.f16.f32 "
        "{%0,%1,%2,%3}, {%4,%5,%6,%7}, {%8,%9}, {%0,%1,%2,%3};"
        : "+f"(c[0]), "+f"(c[1]), "+f"(c[2]), "+f"(c[3])
        : "r"(a[0]), "r"(a[1]), "r"(a[2]), "r"(a[3]), "r"(b[0]), "r"(b[1]));
}
__device__ __forceinline__ void ldsm4(uint32_t* r, uint32_t addr) {
    asm volatile("ldmatrix.sync.aligned.m8n8.x4.shared.b16 {%0,%1,%2,%3}, [%4];"
        : "=r"(r[0]), "=r"(r[1]), "=r"(r[2]), "=r"(r[3]) : "r"(addr));
}
__device__ __forceinline__ void ldsm4t(uint32_t* r, uint32_t addr) {
    asm volatile("ldmatrix.sync.aligned.m8n8.x4.trans.shared.b16 {%0,%1,%2,%3}, [%4];"
        : "=r"(r[0]), "=r"(r[1]), "=r"(r[2]), "=r"(r[3]) : "r"(addr));
}

// fast exp2 on the FMA pipe; valid for x <= 0
__device__ __forceinline__ float fexp2(float x) {
    float y = fmaxf(x, -126.0f);
    float t = y + 12582912.0f;
    float f = y - (t - 12582912.0f);
    int n = __float_as_int(t) - 0x4B400000;
    float p =      1.3333558146e-3f;
    p = fmaf(p, f, 9.6181291076e-3f);
    p = fmaf(p, f, 5.5504108664e-2f);
    p = fmaf(p, f, 2.4022650696e-1f);
    p = fmaf(p, f, 6.9314718056e-1f);
    p = fmaf(p, f, 1.0f);
    return p * __int_as_float((n + 127) << 23);
}

// ---- cp.async helpers ----
__device__ __forceinline__ void cp16(uint32_t dst, const void* src) {
    asm volatile("cp.async.cg.shared.global [%0], [%1], 16;" :: "r"(dst), "l"(src));
}
__device__ __forceinline__ void cp_commit() {
    asm volatile("cp.async.commit_group;" ::: "memory");
}
__device__ __forceinline__ void cp_wait2() {
    asm volatile("cp.async.wait_group 2;" ::: "memory");
}

// fp32 -> fp16 prepass (n multiple of 1024)
__global__ void __launch_bounds__(256)
cvt_fp16(const float* __restrict__ src, __half* __restrict__ dst, int n)
{
    int i = (blockIdx.x * 256 + threadIdx.x) * 4;
    if (i >= n) return;
    float4 v = *(const float4*)(src + i);
    *(__half2*)(dst + i)     = __floats2half2_rn(v.x, v.y);
    *(__half2*)(dst + i + 2) = __floats2half2_rn(v.z, v.w);
}

// mask prepass: fold padding, pre-scale by log2e, store fp16
__global__ void __launch_bounds__(256)
prep_mask(const float* __restrict__ mask, const unsigned char* __restrict__ pad,
          __half* __restrict__ dst)
{
    int i = (blockIdx.x * 256 + threadIdx.x) * 4;
    int b = i / (SEQ * SEQ);
    int c = i & (SEQ - 1);
    float4 m = *(const float4*)(mask + i);
    const unsigned char* pb = pad + b * SEQ + c;
    float v0 = pb[0] ? -14427.0f : m.x * LOG2E;
    float v1 = pb[1] ? -14427.0f : m.y * LOG2E;
    float v2 = pb[2] ? -14427.0f : m.z * LOG2E;
    float v3 = pb[3] ? -14427.0f : m.w * LOG2E;
    *(__half2*)(dst + i)     = __floats2half2_rn(v0, v1);
    *(__half2*)(dst + i + 2) = __floats2half2_rn(v2, v3);
}

// ===== GEMM: EXACT R11 version (known good, 711us config) =====
// C[M,N] = A[M,K] @ W[N,K]^T (+bias). 128x128 tile, BK=32, fp16 mma16816,
// 4-stage cp.async pipeline, one __syncthreads per slab, LDA=40, 2 CTA/SM.
template<int MODE>
__global__ void __launch_bounds__(256, 2)
gemm_fp16(const __half* __restrict__ W,
          const float* __restrict__ bias, float* __restrict__ out)
{
    extern __shared__ __half hs[];
    const int LDA  = 40;
    const int ASTG = 128 * LDA;
    const int NST  = 4;
    const int NSLAB = EMB / 32;          // 32

    const int t    = threadIdx.x;
    const int lane = t & 31, g = lane >> 2, q = lane & 3;
    const int wid  = t >> 5, wm = wid >> 1, wn = wid & 1;
    const int m0   = blockIdx.y * 128;
    const int n0   = blockIdx.x * 128;
    const int ldmr = lane & 15, ldmc = (lane >> 4) * 8;

    const __half* A = (MODE == 0) ? (const __half*)g_qr : (const __half*)g_attn;
    const int lrow = t >> 1;
    const int lcol = (t & 1) * 16;
    const __half* Asrc = A + (size_t)(m0 + lrow) * EMB + lcol;
    const __half* Wsrc = W + (size_t)(n0 + lrow) * EMB + lcol;
    const uint32_t smem0 = (uint32_t)__cvta_generic_to_shared(hs);
    const uint32_t adst0 = smem0 + (lrow * LDA + lcol) * 2;
    const uint32_t bdst0 = smem0 + (NST * ASTG + lrow * LDA + lcol) * 2;
    const uint32_t SSTB  = ASTG * 2;

    float c[2][8][4];
#pragma unroll
    for (int mt = 0; mt < 2; mt++)
#pragma unroll
        for (int nt = 0; nt < 8; nt++)
#pragma unroll
            for (int r = 0; r < 4; r++) c[mt][nt][r] = 0.f;

#pragma unroll
    for (int s = 0; s < 3; s++) {
        const uint32_t so = (uint32_t)s * SSTB;
        cp16(adst0 + so,      Asrc + s * 32);  cp16(adst0 + so + 16, Asrc + s * 32 + 8);
        cp16(bdst0 + so,      Wsrc + s * 32);  cp16(bdst0 + so + 16, Wsrc + s * 32 + 8);
        cp_commit();
    }

    for (int i = 0; i < NSLAB; i++) {
        cp_wait2();
        __syncthreads();
        if (i + 3 < NSLAB) {
            const uint32_t so = (uint32_t)((i + 3) & 3) * SSTB;
            cp16(adst0 + so,      Asrc + (i + 3) * 32);  cp16(adst0 + so + 16, Asrc + (i + 3) * 32 + 8);
            cp16(bdst0 + so,      Wsrc + (i + 3) * 32);  cp16(bdst0 + so + 16, Wsrc + (i + 3) * 32 + 8);
        }
        cp_commit();

        const uint32_t Ast = smem0 + (uint32_t)(i & 3) * SSTB;
        const uint32_t Bst = smem0 + NST * SSTB + (uint32_t)(i & 3) * SSTB;
#pragma unroll
        for (int ks = 0; ks < 2; ks++) {
            uint32_t af[2][4];
#pragma unroll
            for (int mt = 0; mt < 2; mt++)
                ldsm4(af[mt], Ast + ((wm * 32 + mt * 16 + ldmr) * LDA + ks * 16 + ldmc) * 2);
            uint32_t bf[8][2];
#pragma unroll
            for (int n4 = 0; n4 < 4; n4++) {
                uint32_t tmp[4];
                ldsm4(tmp, Bst + ((wn * 64 + n4 * 16 + ldmr) * LDA + ks * 16 + ldmc) * 2);
                bf[n4 * 2][0]     = tmp[0]; bf[n4 * 2][1]     = tmp[2];
                bf[n4 * 2 + 1][0] = tmp[1]; bf[n4 * 2 + 1][1] = tmp[3];
            }
#pragma unroll
            for (int mt = 0; mt < 2; mt++)
#pragma unroll
                for (int nt = 0; nt < 8; nt++)
                    mma16(c[mt][nt], af[mt], bf[nt]);
        }
    }

#pragma unroll
    for (int mt = 0; mt < 2; mt++) {
#pragma unroll
        for (int nt = 0; nt < 8; nt++) {
#pragma unroll
            for (int r = 0; r < 4; r++) {
                const int m = m0 + wm * 32 + mt * 16 + g + ((r >= 2) ? 8 : 0);
                const int n = n0 + wn * 64 + nt * 8 + q * 2 + (r & 1);
                float v = c[mt][nt][r] + bias[n];
                if (MODE == 0) {
                    const int s = m >> 2, b = m & 3;
                    const int which = n >> 10;
                    const int e = n & 1023;
                    const int h = e >> 6, d = e & 63;
                    __half* dst = (which == 0) ? g_q : (which == 1) ? g_k : g_v;
                    if (which == 0) v *= 0.125f * LOG2E;   // D^-0.5 * log2e (exp2 domain)
                    dst[(((b * NHEAD + h) * SEQ) + s) * HDIM + d] = __float2half_rn(v);
                } else {
                    out[(size_t)m * EMB + n] = v;
                }
            }
        }
    }
}

// ===== Flash attention: R11 per-warp structure, q-tile 256 rows / 512 threads =====
// Halves KV L2 traffic (8 q-tile blocks per (b,h) instead of 16). 16 warps/SM
// maintained via 1 CTA/SM x 16 warps. Per-warp register/work profile unchanged.
__global__ void __launch_bounds__(512, 1)
attn_fp16()
{
    extern __shared__ __half hs[];
    const int LD  = 72;
    const int NST = 4;
    const int NKT = SEQ / 64;

    const int t = threadIdx.x, lane = t & 31, g = lane >> 2, q = lane & 3;
    const int wid = t >> 5;                  // 0..15 -> 256 q-rows
    const int qt = blockIdx.x;               // 0..7
    const int bh = blockIdx.y;
    const int b = bh >> 4, head = bh & 15;
    const int ldmr = lane & 15, ldmc = (lane >> 4) * 8;

    const __half* Qg = g_q + (size_t)bh * SEQ * HDIM;
    const __half* Kg = g_k + (size_t)bh * SEQ * HDIM;
    const __half* Vg = g_v + (size_t)bh * SEQ * HDIM;
    const __half* Mg = g_maskh + (size_t)b * SEQ * SEQ + (size_t)(qt * 256) * SEQ;

    const uint32_t s0v = (uint32_t)__cvta_generic_to_shared(hs);
    const uint32_t Qb = s0v;                       // [256][72]
    const uint32_t Kb = s0v + 256 * LD * 2;        // [4][64][72]
    const uint32_t Vb = Kb + NST * 64 * LD * 2;    // [4][64][72]
    const uint32_t KVSTB = 64 * LD * 2;

    // loaders (512 threads): Q row = t>>1 (0..255), half-row seg (t&1)*32 halves.
    // K/V row = t>>3 (0..63), seg = (t&7)*8 halves -> one cp16 each.
    const __half* Qsrc = Qg + (size_t)(qt * 256 + (t >> 1)) * HDIM + (t & 1) * 32;
    const uint32_t qdst = Qb + ((t >> 1) * LD + (t & 1) * 32) * 2;
    const __half* Ksrc = Kg + (size_t)(t >> 3) * HDIM + (t & 7) * 8;
    const __half* Vsrc = Vg + (size_t)(t >> 3) * HDIM + (t & 7) * 8;
    const uint32_t kdst0 = Kb + ((t >> 3) * LD + (t & 7) * 8) * 2;
    const uint32_t vdst0 = Vb + ((t >> 3) * LD + (t & 7) * 8) * 2;

    float o[8][4];
#pragma unroll
    for (int nt = 0; nt < 8; nt++)
#pragma unroll
        for (int r = 0; r < 4; r++) o[nt][r] = 0.f;
    float ol[4] = {0.f, 0.f, 0.f, 0.f};       // ones-column accumulator (row sums)
    float m_i[2] = {-1e30f, -1e30f};
    uint32_t qf[4][4];
    const uint32_t bones[2] = {0x3C003C00u, 0x3C003C00u};   // half2(1,1)

#pragma unroll
    for (int i = 0; i < 4; i++) cp16(qdst + i * 16, Qsrc + i * 8);
#pragma unroll
    for (int s = 0; s < 3; s++) {
        const uint32_t so = (uint32_t)s * KVSTB;
        const size_t goff = (size_t)s * 64 * HDIM;
        cp16(kdst0 + so, Ksrc + goff);
        cp16(vdst0 + so, Vsrc + goff);
        cp_commit();
    }

    for (int kt = 0; kt < NKT; kt++) {
        cp_wait2();
        __syncthreads();

        if (kt == 0) {
#pragma unroll
            for (int ks = 0; ks < 4; ks++)
                ldsm4(qf[ks], Qb + ((wid * 16 + ldmr) * LD + ks * 16 + ldmc) * 2);
        }
        if (kt + 3 < NKT) {
            const uint32_t so = (uint32_t)((kt + 3) & 3) * KVSTB;
            const size_t goff = (size_t)(kt + 3) * 64 * HDIM;
            cp16(kdst0 + so, Ksrc + goff);
            cp16(vdst0 + so, Vsrc + goff);
        }
        cp_commit();

        const uint32_t Kst = Kb + (uint32_t)(kt & 3) * KVSTB;
        const uint32_t Vst = Vb + (uint32_t)(kt & 3) * KVSTB;

        // ---- S = Q K^T (exp2-domain) ----
        float s[8][4];
#pragma unroll
        for (int nt = 0; nt < 8; nt++)
#pragma unroll
            for (int r = 0; r < 4; r++) s[nt][r] = 0.f;
#pragma unroll
        for (int ks = 0; ks < 4; ks++) {
            uint32_t bf[8][2];
#pragma unroll
            for (int n4 = 0; n4 < 4; n4++) {
                uint32_t tmp[4];
                ldsm4(tmp, Kst + ((n4 * 16 + ldmr) * LD + ks * 16 + ldmc) * 2);
                bf[n4 * 2][0]     = tmp[0]; bf[n4 * 2][1]     = tmp[2];
                bf[n4 * 2 + 1][0] = tmp[1]; bf[n4 * 2 + 1][1] = tmp[3];
            }
#pragma unroll
            for (int nt = 0; nt < 8; nt++)
                mma16(s[nt], qf[ks], bf[nt]);
        }

        // ---- mask + online softmax; pack P into A-frags ----
        uint32_t pa_lo[8], pa_hi[8];
        const int kg0 = kt * 64 + 2 * q;
#pragma unroll
        for (int hh = 0; hh < 2; hh++) {
            const int row = wid * 16 + g + hh * 8;
            const __half* Mrow = Mg + (size_t)row * SEQ + kg0;
            float mx = -1e30f;
#pragma unroll
            for (int nt = 0; nt < 8; nt++) {
                float2 mf = __half22float2(*(const __half2*)(Mrow + nt * 8));
                float v0 = s[nt][hh * 2]     + mf.x;
                float v1 = s[nt][hh * 2 + 1] + mf.y;
                s[nt][hh * 2]     = v0;
                s[nt][hh * 2 + 1] = v1;
                mx = fmaxf(mx, fmaxf(v0, v1));
            }
            mx = fmaxf(mx, __shfl_xor_sync(0xffffffffu, mx, 1));
            mx = fmaxf(mx, __shfl_xor_sync(0xffffffffu, mx, 2));
            const float mnew = fmaxf(m_i[hh], mx);
            const float sc = fexp2(m_i[hh] - mnew);
            m_i[hh] = mnew;
#pragma unroll
            for (int nt = 0; nt < 8; nt++) {
                float p0 = fexp2(s[nt][hh * 2]     - mnew);
                float p1 = fexp2(s[nt][hh * 2 + 1] - mnew);
                __half2 ph = __floats2half2_rn(p0, p1);
                if (hh == 0) pa_lo[nt] = reinterpret_cast<uint32_t&>(ph);
                else         pa_hi[nt] = reinterpret_cast<uint32_t&>(ph);
                o[nt][hh * 2]     *= sc;
                o[nt][hh * 2 + 1] *= sc;
            }
            ol[hh * 2] *= sc;            // rescale running row-sum like o
        }

        // ---- O += P V ; row-sums += P·1 (ones-column mma) ----
#pragma unroll
        for (int ks = 0; ks < 4; ks++) {
            uint32_t pa[4];
            pa[0] = pa_lo[2 * ks];     pa[1] = pa_hi[2 * ks];
            pa[2] = pa_lo[2 * ks + 1]; pa[3] = pa_hi[2 * ks + 1];
            uint32_t bf[8][2];
#pragma unroll
            for (int n4 = 0; n4 < 4; n4++) {
                uint32_t tmp[4];
                ldsm4t(tmp, Vst + ((ks * 16 + ldmr) * LD + n4 * 16 + ldmc) * 2);
                bf[n4 * 2][0]     = tmp[0]; bf[n4 * 2][1]     = tmp[1];
                bf[n4 * 2 + 1][0] = tmp[2]; bf[n4 * 2 + 1][1] = tmp[3];
            }
#pragma unroll
            for (int nt = 0; nt < 8; nt++)
                mma16(o[nt], pa, bf[nt]);
            mma16(ol, pa, bones);        // denominator, consistent with fp16 P
        }
    }

    // ---- normalize + write [S,B,E] fp16 for the output GEMM ----
#pragma unroll
    for (int hh = 0; hh < 2; hh++) {
        const float inv = 1.0f / ol[hh * 2];
        const int srow = qt * 256 + wid * 16 + g + hh * 8;
        __half* dst = g_attn + ((size_t)srow * BATCH + b) * EMB + head * HDIM + 2 * q;
#pragma unroll
        for (int nt = 0; nt < 8; nt++) {
            *(__half2*)(dst + nt * 8) =
                __floats2half2_rn(o[nt][hh * 2] * inv, o[nt][hh * 2 + 1] * inv);
        }
    }
}

extern "C" void kernel_launch(void* const* d_in, const int* in_sizes, int n_in,
                              void* d_out, int out_size)
{
    const float* query         = (const float*)d_in[0];
    const float* amask         = (const float*)d_in[1];
    const unsigned char* pmask = (const unsigned char*)d_in[2];
    const float* W_in          = (const float*)d_in[3];
    const float* b_in          = (const float*)d_in[4];
    const float* W_out         = (const float*)d_in[5];
    const float* b_out         = (const float*)d_in[6];
    float* out = (float*)d_out;
    (void)in_sizes; (void)n_in; (void)out_size;

    const int GEMM_SMEM = 8 * 128 * 40 * 2;                     // 81920 B (4 stages A+B)
    const int ATTN_SMEM = (256 * 72 + 8 * 64 * 72) * 2;         // 110592 B
    cudaFuncSetAttribute(gemm_fp16<0>, cudaFuncAttributeMaxDynamicSharedMemorySize, GEMM_SMEM);
    cudaFuncSetAttribute(gemm_fp16<1>, cudaFuncAttributeMaxDynamicSharedMemorySize, GEMM_SMEM);
    cudaFuncSetAttribute(attn_fp16,    cudaFuncAttributeMaxDynamicSharedMemorySize, ATTN_SMEM);

    __half* d_qr; __half* d_winr; __half* d_woutr; __half* d_maskh;
    cudaGetSymbolAddress((void**)&d_qr,    g_qr);
    cudaGetSymbolAddress((void**)&d_winr,  g_winr);
    cudaGetSymbolAddress((void**)&d_woutr, g_woutr);
    cudaGetSymbolAddress((void**)&d_maskh, g_maskh);

    // 0) conversion prepasses (pure HBM)
    cvt_fp16<<<SEQ*BATCH*EMB/1024, 256>>>(query, d_qr,    SEQ*BATCH*EMB);
    cvt_fp16<<<3*EMB*EMB/1024,     256>>>(W_in,  d_winr,  3*EMB*EMB);
    cvt_fp16<<<EMB*EMB/1024,       256>>>(W_out, d_woutr, EMB*EMB);
    prep_mask<<<BATCH*SEQ*SEQ/1024, 256>>>(amask, pmask, d_maskh);

    // 1) QKV projection, fused routing + q scaling (exp2 domain)
    gemm_fp16<0><<<dim3(24, 64), 256, GEMM_SMEM>>>(d_winr, b_in, nullptr);
    // 2) flash attention (256-row q-tiles, halved KV traffic)
    attn_fp16<<<dim3(8, 64), 512, ATTN_SMEM>>>();
    // 3) output projection
    gemm_fp16<1><<<dim3(8, 64), 256, GEMM_SMEM>>>(d_woutr, b_out, out);
}

// round 16
// speedup vs baseline: 1.1546x; 1.1546x over previous
#include <cuda_runtime.h>
#include <cuda_fp16.h>
#include <cstdint>

#define SEQ 2048
#define BATCH 4
#define EMB 1024
#define NHEAD 16
#define HDIM 64
#define LOG2E 1.4426950408889634f

// scratch (static device arrays: allocation-free rule)
__device__ __half g_q[BATCH*NHEAD*SEQ*HDIM];
__device__ __half g_k[BATCH*NHEAD*SEQ*HDIM];
__device__ __half g_v[BATCH*NHEAD*SEQ*HDIM];
__device__ __half g_attn[SEQ*BATCH*EMB];
__device__ __half g_qr [SEQ*BATCH*EMB];
__device__ __half g_winr[3*EMB*EMB];
__device__ __half g_woutr[EMB*EMB];
__device__ __half g_maskh[BATCH*SEQ*SEQ];   // pad-folded, pre-scaled by log2e

// ---- mma.sync / ldmatrix helpers ----
__device__ __forceinline__ void mma16(float* c, const uint32_t* a, const uint32_t* b) {
    asm volatile(
        "mma.sync.aligned.m16n8k16.row.col.f32.f16.f16.f32 "
        "{%0,%1,%2,%3}, {%4,%5,%6,%7}, {%8,%9}, {%0,%1,%2,%3};"
        : "+f"(c[0]), "+f"(c[1]), "+f"(c[2]), "+f"(c[3])
        : "r"(a[0]), "r"(a[1]), "r"(a[2]), "r"(a[3]), "r"(b[0]), "r"(b[1]));
}
__device__ __forceinline__ void ldsm4(uint32_t* r, uint32_t addr) {
    asm volatile("ldmatrix.sync.aligned.m8n8.x4.shared.b16 {%0,%1,%2,%3}, [%4];"
        : "=r"(r[0]), "=r"(r[1]), "=r"(r[2]), "=r"(r[3]) : "r"(addr));
}
__device__ __forceinline__ void ldsm4t(uint32_t* r, uint32_t addr) {
    asm volatile("ldmatrix.sync.aligned.m8n8.x4.trans.shared.b16 {%0,%1,%2,%3}, [%4];"
        : "=r"(r[0]), "=r"(r[1]), "=r"(r[2]), "=r"(r[3]) : "r"(addr));
}

// fast exp2 on the FMA pipe; valid for x <= 0 (scalar, used for sc)
__device__ __forceinline__ float fexp2(float x) {
    float y = fmaxf(x, -126.0f);
    float t = y + 12582912.0f;
    float f = y - (t - 12582912.0f);
    int n = __float_as_int(t) - 0x4B400000;
    float p =      9.6181291076e-3f;
    p = fmaf(p, f, 5.5504108664e-2f);
    p = fmaf(p, f, 2.4022650696e-1f);
    p = fmaf(p, f, 6.9314718056e-1f);
    p = fmaf(p, f, 1.0f);
    return p * __int_as_float((n + 127) << 23);
}

// pack a float into both lanes of an f32x2 register pair
__device__ __forceinline__ unsigned long long pk2(float x) {
    unsigned long long r;
    asm("mov.b64 %0, {%1, %1};" : "=l"(r) : "f"(x));
    return r;
}

// packed exp2 for a pair -> half2 bits (lo = 2^a, hi = 2^b). Degree-4 poly,
// Horner chain on f32x2 ops. Clamp is scalar (max.f32x2 not supported by ptxas
// on this target). Valid for a,b <= 0.
__device__ __forceinline__ uint32_t fexp2h2(float a, float b,
        unsigned long long MG2,
        unsigned long long C4, unsigned long long C3,
        unsigned long long C2, unsigned long long C1,
        unsigned long long ONE2)
{
    a = fmaxf(a, -126.0f);          // scalar clamp (FMNMX, fixed-lat pipe)
    b = fmaxf(b, -126.0f);
    unsigned long long y, t, nf, f, p, s2;
    asm("mov.b64 %0, {%1, %2};" : "=l"(y) : "f"(a), "f"(b));
    asm("add.rn.f32x2 %0, %1, %2;" : "=l"(t) : "l"(y), "l"(MG2));
    asm("sub.rn.f32x2 %0, %1, %2;" : "=l"(nf) : "l"(t), "l"(MG2));
    asm("sub.rn.f32x2 %0, %1, %2;" : "=l"(f) : "l"(y), "l"(nf));
    asm("fma.rn.f32x2 %0, %1, %2, %3;" : "=l"(p) : "l"(C4), "l"(f), "l"(C3));
    asm("fma.rn.f32x2 %0, %1, %2, %3;" : "=l"(p) : "l"(p),  "l"(f), "l"(C2));
    asm("fma.rn.f32x2 %0, %1, %2, %3;" : "=l"(p) : "l"(p),  "l"(f), "l"(C1));
    asm("fma.rn.f32x2 %0, %1, %2, %3;" : "=l"(p) : "l"(p),  "l"(f), "l"(ONE2));
    uint32_t tlo, thi;
    asm("mov.b64 {%0, %1}, %2;" : "=r"(tlo), "=r"(thi) : "l"(t));
    const uint32_t elo = (tlo + 0xB4C0007Fu) << 23;   // ((t-0x4B400000)+127)<<23
    const uint32_t ehi = (thi + 0xB4C0007Fu) << 23;
    asm("mov.b64 %0, {%1, %2};" : "=l"(s2) : "r"(elo), "r"(ehi));
    asm("mul.rn.f32x2 %0, %1, %2;" : "=l"(p) : "l"(p), "l"(s2));
    float r0, r1;
    asm("mov.b64 {%0, %1}, %2;" : "=f"(r0), "=f"(r1) : "l"(p));
    uint32_t h;
    asm("cvt.rn.f16x2.f32 %0, %1, %2;" : "=r"(h) : "f"(r1), "f"(r0));
    return h;
}

// ---- cp.async helpers ----
__device__ __forceinline__ void cp16(uint32_t dst, const void* src) {
    asm volatile("cp.async.cg.shared.global [%0], [%1], 16;" :: "r"(dst), "l"(src));
}
__device__ __forceinline__ void cp_commit() {
    asm volatile("cp.async.commit_group;" ::: "memory");
}
__device__ __forceinline__ void cp_wait2() {
    asm volatile("cp.async.wait_group 2;" ::: "memory");
}

// fp32 -> fp16 prepass (n multiple of 1024)
__global__ void __launch_bounds__(256)
cvt_fp16(const float* __restrict__ src, __half* __restrict__ dst, int n)
{
    int i = (blockIdx.x * 256 + threadIdx.x) * 4;
    if (i >= n) return;
    float4 v = *(const float4*)(src + i);
    *(__half2*)(dst + i)     = __floats2half2_rn(v.x, v.y);
    *(__half2*)(dst + i + 2) = __floats2half2_rn(v.z, v.w);
}

// mask prepass: fold padding, pre-scale by log2e, store fp16
__global__ void __launch_bounds__(256)
prep_mask(const float* __restrict__ mask, const unsigned char* __restrict__ pad,
          __half* __restrict__ dst)
{
    int i = (blockIdx.x * 256 + threadIdx.x) * 4;
    int b = i / (SEQ * SEQ);
    int c = i & (SEQ - 1);
    float4 m = *(const float4*)(mask + i);
    const unsigned char* pb = pad + b * SEQ + c;
    float v0 = pb[0] ? -14427.0f : m.x * LOG2E;
    float v1 = pb[1] ? -14427.0f : m.y * LOG2E;
    float v2 = pb[2] ? -14427.0f : m.z * LOG2E;
    float v3 = pb[3] ? -14427.0f : m.w * LOG2E;
    *(__half2*)(dst + i)     = __floats2half2_rn(v0, v1);
    *(__half2*)(dst + i + 2) = __floats2half2_rn(v2, v3);
}

// ===== GEMM: EXACT R11 version (known good) =====
template<int MODE>
__global__ void __launch_bounds__(256, 2)
gemm_fp16(const __half* __restrict__ W,
          const float* __restrict__ bias, float* __restrict__ out)
{
    extern __shared__ __half hs[];
    const int LDA  = 40;
    const int ASTG = 128 * LDA;
    const int NST  = 4;
    const int NSLAB = EMB / 32;          // 32

    const int t    = threadIdx.x;
    const int lane = t & 31, g = lane >> 2, q = lane & 3;
    const int wid  = t >> 5, wm = wid >> 1, wn = wid & 1;
    const int m0   = blockIdx.y * 128;
    const int n0   = blockIdx.x * 128;
    const int ldmr = lane & 15, ldmc = (lane >> 4) * 8;

    const __half* A = (MODE == 0) ? (const __half*)g_qr : (const __half*)g_attn;
    const int lrow = t >> 1;
    const int lcol = (t & 1) * 16;
    const __half* Asrc = A + (size_t)(m0 + lrow) * EMB + lcol;
    const __half* Wsrc = W + (size_t)(n0 + lrow) * EMB + lcol;
    const uint32_t smem0 = (uint32_t)__cvta_generic_to_shared(hs);
    const uint32_t adst0 = smem0 + (lrow * LDA + lcol) * 2;
    const uint32_t bdst0 = smem0 + (NST * ASTG + lrow * LDA + lcol) * 2;
    const uint32_t SSTB  = ASTG * 2;

    float c[2][8][4];
#pragma unroll
    for (int mt = 0; mt < 2; mt++)
#pragma unroll
        for (int nt = 0; nt < 8; nt++)
#pragma unroll
            for (int r = 0; r < 4; r++) c[mt][nt][r] = 0.f;

#pragma unroll
    for (int s = 0; s < 3; s++) {
        const uint32_t so = (uint32_t)s * SSTB;
        cp16(adst0 + so,      Asrc + s * 32);  cp16(adst0 + so + 16, Asrc + s * 32 + 8);
        cp16(bdst0 + so,      Wsrc + s * 32);  cp16(bdst0 + so + 16, Wsrc + s * 32 + 8);
        cp_commit();
    }

    for (int i = 0; i < NSLAB; i++) {
        cp_wait2();
        __syncthreads();
        if (i + 3 < NSLAB) {
            const uint32_t so = (uint32_t)((i + 3) & 3) * SSTB;
            cp16(adst0 + so,      Asrc + (i + 3) * 32);  cp16(adst0 + so + 16, Asrc + (i + 3) * 32 + 8);
            cp16(bdst0 + so,      Wsrc + (i + 3) * 32);  cp16(bdst0 + so + 16, Wsrc + (i + 3) * 32 + 8);
        }
        cp_commit();

        const uint32_t Ast = smem0 + (uint32_t)(i & 3) * SSTB;
        const uint32_t Bst = smem0 + NST * SSTB + (uint32_t)(i & 3) * SSTB;
#pragma unroll
        for (int ks = 0; ks < 2; ks++) {
            uint32_t af[2][4];
#pragma unroll
            for (int mt = 0; mt < 2; mt++)
                ldsm4(af[mt], Ast + ((wm * 32 + mt * 16 + ldmr) * LDA + ks * 16 + ldmc) * 2);
            uint32_t bf[8][2];
#pragma unroll
            for (int n4 = 0; n4 < 4; n4++) {
                uint32_t tmp[4];
                ldsm4(tmp, Bst + ((wn * 64 + n4 * 16 + ldmr) * LDA + ks * 16 + ldmc) * 2);
                bf[n4 * 2][0]     = tmp[0]; bf[n4 * 2][1]     = tmp[2];
                bf[n4 * 2 + 1][0] = tmp[1]; bf[n4 * 2 + 1][1] = tmp[3];
            }
#pragma unroll
            for (int mt = 0; mt < 2; mt++)
#pragma unroll
                for (int nt = 0; nt < 8; nt++)
                    mma16(c[mt][nt], af[mt], bf[nt]);
        }
    }

#pragma unroll
    for (int mt = 0; mt < 2; mt++) {
#pragma unroll
        for (int nt = 0; nt < 8; nt++) {
#pragma unroll
            for (int r = 0; r < 4; r++) {
                const int m = m0 + wm * 32 + mt * 16 + g + ((r >= 2) ? 8 : 0);
                const int n = n0 + wn * 64 + nt * 8 + q * 2 + (r & 1);
                float v = c[mt][nt][r] + bias[n];
                if (MODE == 0) {
                    const int s = m >> 2, b = m & 3;
                    const int which = n >> 10;
                    const int e = n & 1023;
                    const int h = e >> 6, d = e & 63;
                    __half* dst = (which == 0) ? g_q : (which == 1) ? g_k : g_v;
                    if (which == 0) v *= 0.125f * LOG2E;   // D^-0.5 * log2e (exp2 domain)
                    dst[(((b * NHEAD + h) * SEQ) + s) * HDIM + d] = __float2half_rn(v);
                } else {
                    out[(size_t)m * EMB + n] = v;
                }
            }
        }
    }
}

// ===== Flash attention: R11 structure; ONLY change = packed f32x2 exp2 =====
__global__ void __launch_bounds__(256, 2)
attn_fp16()
{
    extern __shared__ __half hs[];
    const int LD  = 72;
    const int NST = 4;
    const int NKT = SEQ / 64;

    const int t = threadIdx.x, lane = t & 31, g = lane >> 2, q = lane & 3;
    const int wid = t >> 5;
    const int qt = blockIdx.x;
    const int bh = blockIdx.y;
    const int b = bh >> 4, head = bh & 15;
    const int ldmr = lane & 15, ldmc = (lane >> 4) * 8;

    const __half* Qg = g_q + (size_t)bh * SEQ * HDIM;
    const __half* Kg = g_k + (size_t)bh * SEQ * HDIM;
    const __half* Vg = g_v + (size_t)bh * SEQ * HDIM;
    const __half* Mg = g_maskh + (size_t)b * SEQ * SEQ + (size_t)(qt * 128) * SEQ;

    const uint32_t s0v = (uint32_t)__cvta_generic_to_shared(hs);
    const uint32_t Qb = s0v;
    const uint32_t Kb = s0v + 128 * LD * 2;
    const uint32_t Vb = Kb + NST * 64 * LD * 2;
    const uint32_t KVSTB = 64 * LD * 2;

    const __half* Qsrc = Qg + (size_t)(qt * 128 + (t >> 1)) * HDIM + (t & 1) * 32;
    const uint32_t qdst = Qb + ((t >> 1) * LD + (t & 1) * 32) * 2;
    const __half* Ksrc = Kg + (size_t)(t >> 2) * HDIM + (t & 3) * 16;
    const __half* Vsrc = Vg + (size_t)(t >> 2) * HDIM + (t & 3) * 16;
    const uint32_t kdst0 = Kb + ((t >> 2) * LD + (t & 3) * 16) * 2;
    const uint32_t vdst0 = Vb + ((t >> 2) * LD + (t & 3) * 16) * 2;

    // f32x2 constant pairs (hoisted; loop-invariant)
    const unsigned long long MG2  = pk2(12582912.0f);
    const unsigned long long C4e  = pk2(9.6181291076e-3f);
    const unsigned long long C3e  = pk2(5.5504108664e-2f);
    const unsigned long long C2e  = pk2(2.4022650696e-1f);
    const unsigned long long C1e  = pk2(6.9314718056e-1f);
    const unsigned long long ONE2 = pk2(1.0f);

    float o[8][4];
#pragma unroll
    for (int nt = 0; nt < 8; nt++)
#pragma unroll
        for (int r = 0; r < 4; r++) o[nt][r] = 0.f;
    float ol[4] = {0.f, 0.f, 0.f, 0.f};       // ones-column accumulator (row sums)
    float m_i[2] = {-1e30f, -1e30f};
    uint32_t qf[4][4];
    const uint32_t bones[2] = {0x3C003C00u, 0x3C003C00u};   // half2(1,1)

#pragma unroll
    for (int i = 0; i < 4; i++) cp16(qdst + i * 16, Qsrc + i * 8);
#pragma unroll
    for (int s = 0; s < 3; s++) {
        const uint32_t so = (uint32_t)s * KVSTB;
        const size_t goff = (size_t)s * 64 * HDIM;
        cp16(kdst0 + so, Ksrc + goff);  cp16(kdst0 + so + 16, Ksrc + goff + 8);
        cp16(vdst0 + so, Vsrc + goff);  cp16(vdst0 + so + 16, Vsrc + goff + 8);
        cp_commit();
    }

    for (int kt = 0; kt < NKT; kt++) {
        cp_wait2();
        __syncthreads();

        if (kt == 0) {
#pragma unroll
            for (int ks = 0; ks < 4; ks++)
                ldsm4(qf[ks], Qb + ((wid * 16 + ldmr) * LD + ks * 16 + ldmc) * 2);
        }
        if (kt + 3 < NKT) {
            const uint32_t so = (uint32_t)((kt + 3) & 3) * KVSTB;
            const size_t goff = (size_t)(kt + 3) * 64 * HDIM;
            cp16(kdst0 + so, Ksrc + goff);  cp16(kdst0 + so + 16, Ksrc + goff + 8);
            cp16(vdst0 + so, Vsrc + goff);  cp16(vdst0 + so + 16, Vsrc + goff + 8);
        }
        cp_commit();

        const uint32_t Kst = Kb + (uint32_t)(kt & 3) * KVSTB;
        const uint32_t Vst = Vb + (uint32_t)(kt & 3) * KVSTB;

        // ---- S = Q K^T (exp2-domain) ----
        float s[8][4];
#pragma unroll
        for (int nt = 0; nt < 8; nt++)
#pragma unroll
            for (int r = 0; r < 4; r++) s[nt][r] = 0.f;
#pragma unroll
        for (int ks = 0; ks < 4; ks++) {
            uint32_t bf[8][2];
#pragma unroll
            for (int n4 = 0; n4 < 4; n4++) {
                uint32_t tmp[4];
                ldsm4(tmp, Kst + ((n4 * 16 + ldmr) * LD + ks * 16 + ldmc) * 2);
                bf[n4 * 2][0]     = tmp[0]; bf[n4 * 2][1]     = tmp[2];
                bf[n4 * 2 + 1][0] = tmp[1]; bf[n4 * 2 + 1][1] = tmp[3];
            }
#pragma unroll
            for (int nt = 0; nt < 8; nt++)
                mma16(s[nt], qf[ks], bf[nt]);
        }

        // ---- mask + online softmax; pack P into A-frags (packed exp2) ----
        uint32_t pa_lo[8], pa_hi[8];
        const int kg0 = kt * 64 + 2 * q;
#pragma unroll
        for (int hh = 0; hh < 2; hh++) {
            const int row = wid * 16 + g + hh * 8;
            const __half* Mrow = Mg + (size_t)row * SEQ + kg0;
            float mx = -1e30f;
#pragma unroll
            for (int nt = 0; nt < 8; nt++) {
                float2 mf = __half22float2(*(const __half2*)(Mrow + nt * 8));
                float v0 = s[nt][hh * 2]     + mf.x;
                float v1 = s[nt][hh * 2 + 1] + mf.y;
                s[nt][hh * 2]     = v0;
                s[nt][hh * 2 + 1] = v1;
                mx = fmaxf(mx, fmaxf(v0, v1));
            }
            mx = fmaxf(mx, __shfl_xor_sync(0xffffffffu, mx, 1));
            mx = fmaxf(mx, __shfl_xor_sync(0xffffffffu, mx, 2));
            const float mnew = fmaxf(m_i[hh], mx);
            const float sc = fexp2(m_i[hh] - mnew);
            m_i[hh] = mnew;
#pragma unroll
            for (int nt = 0; nt < 8; nt++) {
                const uint32_t ph = fexp2h2(s[nt][hh * 2] - mnew,
                                            s[nt][hh * 2 + 1] - mnew,
                                            MG2, C4e, C3e, C2e, C1e, ONE2);
                if (hh == 0) pa_lo[nt] = ph;
                else         pa_hi[nt] = ph;
                o[nt][hh * 2]     *= sc;
                o[nt][hh * 2 + 1] *= sc;
            }
            ol[hh * 2] *= sc;            // rescale running row-sum like o
        }

        // ---- O += P V ; row-sums += P·1 (ones-column mma) ----
#pragma unroll
        for (int ks = 0; ks < 4; ks++) {
            uint32_t pa[4];
            pa[0] = pa_lo[2 * ks];     pa[1] = pa_hi[2 * ks];
            pa[2] = pa_lo[2 * ks + 1]; pa[3] = pa_hi[2 * ks + 1];
            uint32_t bf[8][2];
#pragma unroll
            for (int n4 = 0; n4 < 4; n4++) {
                uint32_t tmp[4];
                ldsm4t(tmp, Vst + ((ks * 16 + ldmr) * LD + n4 * 16 + ldmc) * 2);
                bf[n4 * 2][0]     = tmp[0]; bf[n4 * 2][1]     = tmp[1];
                bf[n4 * 2 + 1][0] = tmp[2]; bf[n4 * 2 + 1][1] = tmp[3];
            }
#pragma unroll
            for (int nt = 0; nt < 8; nt++)
                mma16(o[nt], pa, bf[nt]);
            mma16(ol, pa, bones);        // denominator, consistent with fp16 P
        }
    }

    // ---- normalize + write [S,B,E] fp16 for the output GEMM ----
#pragma unroll
    for (int hh = 0; hh < 2; hh++) {
        const float inv = 1.0f / ol[hh * 2];
        const int srow = qt * 128 + wid * 16 + g + hh * 8;
        __half* dst = g_attn + ((size_t)srow * BATCH + b) * EMB + head * HDIM + 2 * q;
#pragma unroll
        for (int nt = 0; nt < 8; nt++) {
            *(__half2*)(dst + nt * 8) =
                __floats2half2_rn(o[nt][hh * 2] * inv, o[nt][hh * 2 + 1] * inv);
        }
    }
}

extern "C" void kernel_launch(void* const* d_in, const int* in_sizes, int n_in,
                              void* d_out, int out_size)
{
    const float* query         = (const float*)d_in[0];
    const float* amask         = (const float*)d_in[1];
    const unsigned char* pmask = (const unsigned char*)d_in[2];
    const float* W_in          = (const float*)d_in[3];
    const float* b_in          = (const float*)d_in[4];
    const float* W_out         = (const float*)d_in[5];
    const float* b_out         = (const float*)d_in[6];
    float* out = (float*)d_out;
    (void)in_sizes; (void)n_in; (void)out_size;

    const int GEMM_SMEM = 8 * 128 * 40 * 2;                     // 81920 B (4 stages A+B)
    const int ATTN_SMEM = (128 * 72 + 8 * 64 * 72) * 2;         // 92160 B
    cudaFuncSetAttribute(gemm_fp16<0>, cudaFuncAttributeMaxDynamicSharedMemorySize, GEMM_SMEM);
    cudaFuncSetAttribute(gemm_fp16<1>, cudaFuncAttributeMaxDynamicSharedMemorySize, GEMM_SMEM);
    cudaFuncSetAttribute(attn_fp16,    cudaFuncAttributeMaxDynamicSharedMemorySize, ATTN_SMEM);

    __half* d_qr; __half* d_winr; __half* d_woutr; __half* d_maskh;
    cudaGetSymbolAddress((void**)&d_qr,    g_qr);
    cudaGetSymbolAddress((void**)&d_winr,  g_winr);
    cudaGetSymbolAddress((void**)&d_woutr, g_woutr);
    cudaGetSymbolAddress((void**)&d_maskh, g_maskh);

    // 0) conversion prepasses (pure HBM)
    cvt_fp16<<<SEQ*BATCH*EMB/1024, 256>>>(query, d_qr,    SEQ*BATCH*EMB);
    cvt_fp16<<<3*EMB*EMB/1024,     256>>>(W_in,  d_winr,  3*EMB*EMB);
    cvt_fp16<<<EMB*EMB/1024,       256>>>(W_out, d_woutr, EMB*EMB);
    prep_mask<<<BATCH*SEQ*SEQ/1024, 256>>>(amask, pmask, d_maskh);

    // 1) QKV projection, fused routing + q scaling (exp2 domain)
    gemm_fp16<0><<<dim3(24, 64), 256, GEMM_SMEM>>>(d_winr, b_in, nullptr);
    // 2) flash attention (packed f32x2 softmax)
    attn_fp16<<<dim3(16, 64), 256, ATTN_SMEM>>>();
    // 3) output projection
    gemm_fp16<1><<<dim3(8, 64), 256, GEMM_SMEM>>>(d_woutr, b_out, out);
}